// round 13
// baseline (speedup 1.0000x reference)
#include <cuda_runtime.h>
#include <cuda_bf16.h>
#include <cstdint>

// ============================================================================
// scores[b,l] = sum_d tanh( (enc[b,l,:] @ W1_e)[d] + dec_proj[b,d] + b1[d] ) * w2[d]
// out = softmax(scores, axis=-1).  B=32, LIN=2048, E=D=512, nd=1024.
//
// R13: merged producer/consumer GEMM with device-side per-tile flags.
//   bids [0,512):    producer = conv GEMM (cu=0) + publish bf16 A tiles
//   bids [512,2048): consumer = fast GEMM (cu=1..3), cu-inner (3 per rc adjacent)
// Producers dispatch before consumers (lower bids); consumers spin on
// ld.acquire flags (per k-tile) -> no kernel boundary, L2-warm tile handoff.
// ============================================================================

__device__ __align__(16) __nv_bfloat16 g_W1Tb[512 * 512];   // W1_e^T bf16 [d][k]
__device__ __align__(16) float g_dpp[1024 * 512];           // dec_proj partials [b*32+kc][d]
__device__ __align__(16) float g_spart[4u * 65536u];        // per-colunit partial scores
__device__ __align__(16) char  g_encb[512u * 131072u];      // 64MB pre-swizzled bf16 A tiles
__device__ int g_flag[512];                                 // per-rc published tile count

// ---------------------------------------------------------------------------
// helpers
// ---------------------------------------------------------------------------
__device__ __forceinline__ uint32_t smem_u32(const void* p) {
    uint32_t a;
    asm("{ .reg .u64 t; cvta.to.shared.u64 t, %1; cvt.u32.u64 %0, t; }" : "=r"(a) : "l"(p));
    return a;
}
__device__ __forceinline__ void cp_async16(uint32_t sdst, const void* gsrc) {
    asm volatile("cp.async.cg.shared.global [%0], [%1], 16;" :: "r"(sdst), "l"(gsrc) : "memory");
}
#define CP_COMMIT() asm volatile("cp.async.commit_group;" ::: "memory")
#define CP_WAIT(n)  asm volatile("cp.async.wait_group %0;" :: "n"(n) : "memory")

__device__ __forceinline__ float tanh_fast(float x) {
    float t;
    asm("tanh.approx.f32 %0, %1;" : "=f"(t) : "f"(x));
    return t;
}
__device__ __forceinline__ void ldmatrix_x4(uint32_t r[4], uint32_t addr) {
    asm volatile("ldmatrix.sync.aligned.m8n8.x4.shared.b16 {%0,%1,%2,%3}, [%4];"
                 : "=r"(r[0]), "=r"(r[1]), "=r"(r[2]), "=r"(r[3]) : "r"(addr));
}
__device__ __forceinline__ void mma_bf16(float c[4], const uint32_t a[4], const uint32_t b[2]) {
    asm volatile(
        "mma.sync.aligned.m16n8k16.row.col.f32.bf16.bf16.f32 "
        "{%0,%1,%2,%3}, {%4,%5,%6,%7}, {%8,%9}, {%0,%1,%2,%3};"
        : "+f"(c[0]), "+f"(c[1]), "+f"(c[2]), "+f"(c[3])
        : "r"(a[0]), "r"(a[1]), "r"(a[2]), "r"(a[3]), "r"(b[0]), "r"(b[1]));
}
__device__ __forceinline__ int ld_acquire(const int* p) {
    int v;
    asm volatile("ld.global.acquire.gpu.b32 %0, [%1];" : "=r"(v) : "l"(p) : "memory");
    return v;
}
__device__ __forceinline__ void st_release(int* p, int v) {
    asm volatile("st.global.release.gpu.b32 [%0], %1;" :: "l"(p), "r"(v) : "memory");
}

// ---------------------------------------------------------------------------
// Kernel P: prep.
//   [0,1024): dec_proj partials (b x 32 k-chunks of 32); [1024,1280): W1_e^T;
//   [1280,1282): zero g_flag (must be reset every launch for graph replays).
// ---------------------------------------------------------------------------
__global__ void __launch_bounds__(256) prep_kernel(
    const float* __restrict__ W1, const float* __restrict__ dh) {
    int bid = blockIdx.x, tid = threadIdx.x;
    if (bid >= 1280) {
        g_flag[(bid - 1280) * 256 + tid] = 0;
    } else if (bid >= 1024) {
        __shared__ float tile[32][33];
        int v = bid - 1024;
        int d0 = (v & 15) * 32, k0 = (v >> 4) * 32;
        int tx = tid & 31, ty = tid >> 5;
#pragma unroll
        for (int j = 0; j < 32; j += 8)
            tile[ty + j][tx] = W1[(size_t)(1024 + k0 + ty + j) * 512 + d0 + tx];
        __syncthreads();
#pragma unroll
        for (int j = 0; j < 32; j += 8)
            g_W1Tb[(size_t)(d0 + ty + j) * 512 + k0 + tx] = __float2bfloat16_rn(tile[tx][ty + j]);
    } else {
        __shared__ float sdf[32];
        int b = bid >> 5, kc = bid & 31;
        int k0 = kc * 32;
        if (tid < 32) sdf[tid] = dh[b * 1024 + k0 + tid];
        __syncthreads();
        const float* w0 = W1 + (size_t)k0 * 512 + tid;
        const float* w1 = w0 + 256;
        float a[4] = {0.f, 0.f, 0.f, 0.f};
#pragma unroll 4
        for (int k = 0; k < 32; k += 2) {
            a[0] = fmaf(sdf[k],     w0[(size_t)k * 512],       a[0]);
            a[1] = fmaf(sdf[k + 1], w0[(size_t)(k + 1) * 512], a[1]);
            a[2] = fmaf(sdf[k],     w1[(size_t)k * 512],       a[2]);
            a[3] = fmaf(sdf[k + 1], w1[(size_t)(k + 1) * 512], a[3]);
        }
        g_dpp[(size_t)bid * 512 + tid]       = a[0] + a[1];
        g_dpp[(size_t)bid * 512 + tid + 256] = a[2] + a[3];
    }
}

// shared add_s/w2_s loader (sums 32 partials)
__device__ __forceinline__ void load_addw2(float* add_s, float* w2_s, int b, int cu,
                                           const float* b1, const float* w2, int tid) {
    if (tid < 128) {
        int d = cu * 128 + tid;
        float s0 = 0.f, s1 = 0.f, s2 = 0.f, s3 = 0.f;
#pragma unroll
        for (int kc = 0; kc < 32; kc += 4) {
            s0 += g_dpp[(size_t)(b * 32 + kc + 0) * 512 + d];
            s1 += g_dpp[(size_t)(b * 32 + kc + 1) * 512 + d];
            s2 += g_dpp[(size_t)(b * 32 + kc + 2) * 512 + d];
            s3 += g_dpp[(size_t)(b * 32 + kc + 3) * 512 + d];
        }
        add_s[tid] = (s0 + s1) + (s2 + s3) + b1[d];
        w2_s[tid]  = w2[d];
    }
}

// ---------------------------------------------------------------------------
// Kernel M: merged producer/consumer GEMM. Grid 2048, 256 thr, occ 2, 100KB.
// smem (both paths, B at same offset):
//   aux 4KB | conv: A32 32KB @4096, A16 16KB @36864, B 2x16KB @53248
//            | fast: A16 3x16KB @4096,               B 3x16KB @53248
// ---------------------------------------------------------------------------
static constexpr uint32_t AUX_SZ    = 4096;
static constexpr uint32_t C_OFF_A32 = AUX_SZ;             // 32KB (conv)
static constexpr uint32_t C_OFF_A16 = C_OFF_A32 + 32768;  // 16KB (conv)
static constexpr uint32_t F_OFF_A16 = AUX_SZ;             // 3x16KB (fast)
static constexpr uint32_t OFF_B     = 53248;              // 2or3 x 16KB
static constexpr uint32_t SMEM_MAIN = OFF_B + 49152;      // 102400

__global__ void __launch_bounds__(256, 2)
attn_main_kernel(const float* __restrict__ enc, const float* __restrict__ b1,
                 const float* __restrict__ w2) {
    extern __shared__ char sm[];
    float* add_s = (float*)sm;
    float* w2_s  = (float*)(sm + 512);
    float* spart = (float*)(sm + 1024);
    const uint32_t smu = smem_u32(sm);
    const uint32_t bu  = smu + OFF_B;

    const int tid  = threadIdx.x;
    const int lane = tid & 31, wid = tid >> 5;
    const int wm   = wid & 1, wn = wid >> 1;
    const int quad = lane >> 2, qlane = lane & 3;
    const int lane7 = lane & 7;

    const int bid = blockIdx.x;
    const bool producer = (bid < 512);
    const int rc = producer ? bid : (bid - 512) / 3;
    const int cu = producer ? 0 : 1 + (bid - 512) % 3;
    const size_t row0 = (size_t)rc * 128;
    const __nv_bfloat16* gB = g_W1Tb + (size_t)(cu * 128) * 512;
    const int b = rc >> 4;

    load_addw2(add_s, w2_s, b, cu, b1, w2, tid);

    float acc[4][4][4];
#pragma unroll
    for (int mf = 0; mf < 4; mf++)
#pragma unroll
        for (int nf = 0; nf < 4; nf++)
#pragma unroll
            for (int k = 0; k < 4; k++) acc[mf][nf][k] = 0.f;

    const uint32_t a_row = (uint32_t)(wm * 64 + ((lane >> 3) & 1) * 8 + lane7);
    const uint32_t b_row = (uint32_t)(wn * 32 + (lane >> 4) * 8 + lane7);

    if (producer) {
        // ===================== producer: conv GEMM (cu=0) ====================
        const float* gA = enc + row0 * 512;
        const uint32_t a32u = smu + C_OFF_A32;
        const uint32_t a16u = smu + C_OFF_A16;
        char* genc_rc = g_encb + (size_t)rc * 131072;

        auto prefetchA = [&](int t) {
            const float* src = gA + t * 64;
#pragma unroll
            for (int p = 0; p < 8; p++) {
                int slot = tid + p * 256;
                int r = slot >> 4, c = slot & 15;
                cp_async16(a32u + (uint32_t)slot * 16, src + (size_t)r * 512 + c * 4);
            }
        };
        auto prefetchB = [&](int t) {
            uint32_t dst = bu + (uint32_t)(t & 1) * 16384;
            const __nv_bfloat16* src = gB + t * 64;
#pragma unroll
            for (int p = 0; p < 4; p++) {
                int slot = tid + p * 256;
                int r = slot >> 3, blk = slot & 7;
                cp_async16(dst + (uint32_t)(r * 128 + ((blk ^ (r & 7)) << 4)),
                           src + (size_t)r * 512 + blk * 8);
            }
        };

        prefetchA(0); prefetchB(0); CP_COMMIT();

#pragma unroll 1
        for (int i = 0; i < 8; i++) {
            CP_WAIT(0);
            __syncthreads();

            // convert A32 -> A16 (swizzled) + mirror to g_encb (16B per slot)
            char* gdst = genc_rc + (size_t)i * 16384;
#pragma unroll
            for (int p = 0; p < 4; p++) {
                int slot = tid + p * 256;
                int r = slot >> 3, blk = slot & 7;
                const char* src = sm + C_OFF_A32 + (uint32_t)(r * 256 + blk * 32);
                float4 va = *(const float4*)src;
                float4 vb = *(const float4*)(src + 16);
                __nv_bfloat162 q0 = __float22bfloat162_rn({va.x, va.y});
                __nv_bfloat162 q1 = __float22bfloat162_rn({va.z, va.w});
                __nv_bfloat162 q2 = __float22bfloat162_rn({vb.x, vb.y});
                __nv_bfloat162 q3 = __float22bfloat162_rn({vb.z, vb.w});
                uint4 o;
                o.x = *(uint32_t*)&q0; o.y = *(uint32_t*)&q1;
                o.z = *(uint32_t*)&q2; o.w = *(uint32_t*)&q3;
                uint32_t off = (uint32_t)(r * 128 + ((blk ^ (r & 7)) << 4));
                *(uint4*)(sm + C_OFF_A16 + off) = o;
                *(uint4*)(gdst + off) = o;
            }
            __syncthreads();
            if (tid == 0) {                    // publish tile i (cumulative fence)
                __threadfence();
                st_release(&g_flag[rc], i + 1);
            }

            if (i < 7) { prefetchA(i + 1); prefetchB(i + 1); CP_COMMIT(); }
            else CP_COMMIT();

            uint32_t sB = bu + (uint32_t)(i & 1) * 16384;
#pragma unroll
            for (int kf = 0; kf < 4; kf++) {
                uint32_t afr[4][4], bfr[4][2];
                uint32_t ablk = (uint32_t)(((kf * 2 + (lane >> 4)) ^ lane7) << 4);
                uint32_t bblk = (uint32_t)(((kf * 2 + ((lane >> 3) & 1)) ^ lane7) << 4);
#pragma unroll
                for (int mf = 0; mf < 4; mf++)
                    ldmatrix_x4(afr[mf], a16u + (a_row + mf * 16) * 128 + ablk);
#pragma unroll
                for (int j = 0; j < 2; j++) {
                    uint32_t r[4];
                    ldmatrix_x4(r, sB + (b_row + j * 16) * 128 + bblk);
                    bfr[2 * j][0] = r[0];     bfr[2 * j][1] = r[1];
                    bfr[2 * j + 1][0] = r[2]; bfr[2 * j + 1][1] = r[3];
                }
#pragma unroll
                for (int mf = 0; mf < 4; mf++)
#pragma unroll
                    for (int nf = 0; nf < 4; nf++)
                        mma_bf16(acc[mf][nf], afr[mf], bfr[nf]);
            }
        }
    } else {
        // ===================== consumer: fast GEMM (cu=1..3) ================
        const char* gA = g_encb + (size_t)rc * 131072;
        const uint32_t a16u = smu + F_OFF_A16;
        const int* flag = &g_flag[rc];

        auto wait_tile = [&](int t) {          // all threads spin (bcast line)
            while (ld_acquire(flag) < t + 1) { }
        };
        auto prefetch = [&](int t) {
            uint32_t sA = a16u + (uint32_t)(t % 3) * 16384;
            uint32_t sB = bu + (uint32_t)(t % 3) * 16384;
            const char* srcA = gA + (size_t)t * 16384;
            const __nv_bfloat16* srcB = gB + t * 64;
#pragma unroll
            for (int p = 0; p < 4; p++) {
                int slot = tid + p * 256;
                cp_async16(sA + (uint32_t)slot * 16, srcA + (size_t)slot * 16);
                int r = slot >> 3, blk = slot & 7;
                cp_async16(sB + (uint32_t)(r * 128 + ((blk ^ (r & 7)) << 4)),
                           srcB + (size_t)r * 512 + blk * 8);
            }
            CP_COMMIT();
        };

        wait_tile(0); prefetch(0);
        wait_tile(1); prefetch(1);

#pragma unroll 1
        for (int i = 0; i < 8; i++) {
            CP_WAIT(1);
            __syncthreads();
            uint32_t sA = a16u + (uint32_t)(i % 3) * 16384;
            uint32_t sB = bu + (uint32_t)(i % 3) * 16384;

#pragma unroll
            for (int kf = 0; kf < 4; kf++) {
                uint32_t afr[4][4], bfr[4][2];
                uint32_t ablk = (uint32_t)(((kf * 2 + (lane >> 4)) ^ lane7) << 4);
                uint32_t bblk = (uint32_t)(((kf * 2 + ((lane >> 3) & 1)) ^ lane7) << 4);
#pragma unroll
                for (int mf = 0; mf < 4; mf++)
                    ldmatrix_x4(afr[mf], sA + (a_row + mf * 16) * 128 + ablk);
#pragma unroll
                for (int j = 0; j < 2; j++) {
                    uint32_t r[4];
                    ldmatrix_x4(r, sB + (b_row + j * 16) * 128 + bblk);
                    bfr[2 * j][0] = r[0];     bfr[2 * j][1] = r[1];
                    bfr[2 * j + 1][0] = r[2]; bfr[2 * j + 1][1] = r[3];
                }
#pragma unroll
                for (int mf = 0; mf < 4; mf++)
#pragma unroll
                    for (int nf = 0; nf < 4; nf++)
                        mma_bf16(acc[mf][nf], afr[mf], bfr[nf]);
            }

            if (i + 2 < 8) { wait_tile(i + 2); prefetch(i + 2); }
            else CP_COMMIT();
        }
        CP_WAIT(0);
    }

    // ---- shared epilogue: tanh(acc + add) * w2, reduce over cu's 128 cols ----
#pragma unroll
    for (int mf = 0; mf < 4; mf++) {
        float s0 = 0.f, s1 = 0.f;
#pragma unroll
        for (int nf = 0; nf < 4; nf++) {
            int c = wn * 32 + nf * 8 + qlane * 2;
            float a0 = add_s[c], a1 = add_s[c + 1];
            float v0 = w2_s[c],  v1 = w2_s[c + 1];
            s0 = fmaf(tanh_fast(acc[mf][nf][0] + a0), v0, s0);
            s0 = fmaf(tanh_fast(acc[mf][nf][1] + a1), v1, s0);
            s1 = fmaf(tanh_fast(acc[mf][nf][2] + a0), v0, s1);
            s1 = fmaf(tanh_fast(acc[mf][nf][3] + a1), v1, s1);
        }
        s0 += __shfl_xor_sync(0xffffffffu, s0, 1);
        s0 += __shfl_xor_sync(0xffffffffu, s0, 2);
        s1 += __shfl_xor_sync(0xffffffffu, s1, 1);
        s1 += __shfl_xor_sync(0xffffffffu, s1, 2);
        if (qlane == 0) {
            int r = wm * 64 + mf * 16 + quad;
            spart[wn * 128 + r]     = s0;
            spart[wn * 128 + r + 8] = s1;
        }
    }
    __syncthreads();
    if (tid < 128)
        g_spart[(size_t)cu * 65536 + row0 + tid] =
            spart[tid] + spart[128 + tid] + spart[256 + tid] + spart[384 + tid];
}

// ---------------------------------------------------------------------------
// Kernel S: sum 4 partials + row softmax. 32 blocks x 1024 threads.
// ---------------------------------------------------------------------------
__global__ void __launch_bounds__(1024) softmax_kernel(float* __restrict__ out) {
    __shared__ float red[32];
    int b = blockIdx.x, t = threadIdx.x;
    int lane = t & 31, w = t >> 5;
    size_t i0 = (size_t)b * 2048 + t;
    size_t i1 = i0 + 1024;
    float v0 = g_spart[i0] + g_spart[65536 + i0] + g_spart[131072 + i0] + g_spart[196608 + i0];
    float v1 = g_spart[i1] + g_spart[65536 + i1] + g_spart[131072 + i1] + g_spart[196608 + i1];

    float vmax = fmaxf(v0, v1);
#pragma unroll
    for (int off = 16; off > 0; off >>= 1)
        vmax = fmaxf(vmax, __shfl_xor_sync(0xffffffffu, vmax, off));
    if (lane == 0) red[w] = vmax;
    __syncthreads();
    if (t < 32) {
        float m = red[t];
#pragma unroll
        for (int off = 16; off > 0; off >>= 1)
            m = fmaxf(m, __shfl_xor_sync(0xffffffffu, m, off));
        red[t] = m;
    }
    __syncthreads();
    vmax = red[0];
    __syncthreads();

    float e0 = __expf(v0 - vmax), e1 = __expf(v1 - vmax);
    float s = e0 + e1;
#pragma unroll
    for (int off = 16; off > 0; off >>= 1)
        s += __shfl_xor_sync(0xffffffffu, s, off);
    if (lane == 0) red[w] = s;
    __syncthreads();
    if (t < 32) {
        float m = red[t];
#pragma unroll
        for (int off = 16; off > 0; off >>= 1)
            m += __shfl_xor_sync(0xffffffffu, m, off);
        red[t] = m;
    }
    __syncthreads();
    float inv = 1.0f / red[0];

    out[i0] = e0 * inv;
    out[i1] = e1 * inv;
}

// ---------------------------------------------------------------------------
// kernel_launch — inputs: d_hidden, encoder_outputs, W1, b1, w2
// ---------------------------------------------------------------------------
extern "C" void kernel_launch(void* const* d_in, const int* in_sizes, int n_in,
                              void* d_out, int out_size) {
    const float* dh  = (const float*)d_in[0];  // (32, 2, 512)
    const float* enc = (const float*)d_in[1];  // (32, 2048, 512)
    const float* W1  = (const float*)d_in[2];  // (1536, 512)
    const float* b1  = (const float*)d_in[3];  // (512,)
    const float* w2  = (const float*)d_in[4];  // (512,)
    float* out = (float*)d_out;                // (32, 2048)

    cudaFuncSetAttribute(attn_main_kernel, cudaFuncAttributeMaxDynamicSharedMemorySize,
                         (int)SMEM_MAIN);

    prep_kernel<<<1282, 256>>>(W1, dh);
    attn_main_kernel<<<2048, 256, SMEM_MAIN>>>(enc, b1, w2);
    softmax_kernel<<<32, 1024>>>(out);
}

// round 14
// speedup vs baseline: 1.0486x; 1.0486x over previous
#include <cuda_runtime.h>
#include <cuda_bf16.h>
#include <cstdint>

// ============================================================================
// scores[b,l] = sum_d tanh( (enc[b,l,:] @ W1_e)[d] + dec_proj[b,d] + b1[d] ) * w2[d]
// out = softmax(scores, axis=-1).  B=32, LIN=2048, E=D=512, nd=1024.
//
// R14: consolidation of best-measured components.
//   prep    = R13's fine-split (9.0us)
//   conv    = R11's converter GEMM (cu=0, mirrors bf16 tiles to g_encb)
//   fast    = R11's consumer GEMM, rc-major order (3 cus of an rc co-scheduled
//             -> one L2 tile read serves 3 CTAs)
//   softmax = R12's 1024-thread shuffle version (5.6us)
// ============================================================================

__device__ __align__(16) __nv_bfloat16 g_W1Tb[512 * 512];   // W1_e^T bf16 [d][k]
__device__ __align__(16) float g_dpp[1024 * 512];           // dec_proj partials [b*32+kc][d]
__device__ __align__(16) float g_spart[4u * 65536u];        // per-colunit partial scores
__device__ __align__(16) char  g_encb[512u * 131072u];      // 64MB pre-swizzled bf16 A tiles

// ---------------------------------------------------------------------------
// helpers
// ---------------------------------------------------------------------------
__device__ __forceinline__ uint32_t smem_u32(const void* p) {
    uint32_t a;
    asm("{ .reg .u64 t; cvta.to.shared.u64 t, %1; cvt.u32.u64 %0, t; }" : "=r"(a) : "l"(p));
    return a;
}
__device__ __forceinline__ void cp_async16(uint32_t sdst, const void* gsrc) {
    asm volatile("cp.async.cg.shared.global [%0], [%1], 16;" :: "r"(sdst), "l"(gsrc) : "memory");
}
#define CP_COMMIT() asm volatile("cp.async.commit_group;" ::: "memory")
#define CP_WAIT(n)  asm volatile("cp.async.wait_group %0;" :: "n"(n) : "memory")

__device__ __forceinline__ float tanh_fast(float x) {
    float t;
    asm("tanh.approx.f32 %0, %1;" : "=f"(t) : "f"(x));
    return t;
}
__device__ __forceinline__ void ldmatrix_x4(uint32_t r[4], uint32_t addr) {
    asm volatile("ldmatrix.sync.aligned.m8n8.x4.shared.b16 {%0,%1,%2,%3}, [%4];"
                 : "=r"(r[0]), "=r"(r[1]), "=r"(r[2]), "=r"(r[3]) : "r"(addr));
}
__device__ __forceinline__ void mma_bf16(float c[4], const uint32_t a[4], const uint32_t b[2]) {
    asm volatile(
        "mma.sync.aligned.m16n8k16.row.col.f32.bf16.bf16.f32 "
        "{%0,%1,%2,%3}, {%4,%5,%6,%7}, {%8,%9}, {%0,%1,%2,%3};"
        : "+f"(c[0]), "+f"(c[1]), "+f"(c[2]), "+f"(c[3])
        : "r"(a[0]), "r"(a[1]), "r"(a[2]), "r"(a[3]), "r"(b[0]), "r"(b[1]));
}

// ---------------------------------------------------------------------------
// Kernel P: prep.
//   [0,1024): dec_proj partials (b x 32 k-chunks of 32); [1024,1280): W1_e^T.
// ---------------------------------------------------------------------------
__global__ void __launch_bounds__(256) prep_kernel(
    const float* __restrict__ W1, const float* __restrict__ dh) {
    int bid = blockIdx.x, tid = threadIdx.x;
    if (bid >= 1024) {
        __shared__ float tile[32][33];
        int v = bid - 1024;
        int d0 = (v & 15) * 32, k0 = (v >> 4) * 32;
        int tx = tid & 31, ty = tid >> 5;
#pragma unroll
        for (int j = 0; j < 32; j += 8)
            tile[ty + j][tx] = W1[(size_t)(1024 + k0 + ty + j) * 512 + d0 + tx];
        __syncthreads();
#pragma unroll
        for (int j = 0; j < 32; j += 8)
            g_W1Tb[(size_t)(d0 + ty + j) * 512 + k0 + tx] = __float2bfloat16_rn(tile[tx][ty + j]);
    } else {
        __shared__ float sdf[32];
        int b = bid >> 5, kc = bid & 31;
        int k0 = kc * 32;
        if (tid < 32) sdf[tid] = dh[b * 1024 + k0 + tid];
        __syncthreads();
        const float* w0 = W1 + (size_t)k0 * 512 + tid;
        const float* w1 = w0 + 256;
        float a[4] = {0.f, 0.f, 0.f, 0.f};
#pragma unroll 4
        for (int k = 0; k < 32; k += 2) {
            a[0] = fmaf(sdf[k],     w0[(size_t)k * 512],       a[0]);
            a[1] = fmaf(sdf[k + 1], w0[(size_t)(k + 1) * 512], a[1]);
            a[2] = fmaf(sdf[k],     w1[(size_t)k * 512],       a[2]);
            a[3] = fmaf(sdf[k + 1], w1[(size_t)(k + 1) * 512], a[3]);
        }
        g_dpp[(size_t)bid * 512 + tid]       = a[0] + a[1];
        g_dpp[(size_t)bid * 512 + tid + 256] = a[2] + a[3];
    }
}

// shared add_s/w2_s loader (sums 32 partials)
__device__ __forceinline__ void load_addw2(float* add_s, float* w2_s, int b, int cu,
                                           const float* b1, const float* w2, int tid) {
    if (tid < 128) {
        int d = cu * 128 + tid;
        float s0 = 0.f, s1 = 0.f, s2 = 0.f, s3 = 0.f;
#pragma unroll
        for (int kc = 0; kc < 32; kc += 4) {
            s0 += g_dpp[(size_t)(b * 32 + kc + 0) * 512 + d];
            s1 += g_dpp[(size_t)(b * 32 + kc + 1) * 512 + d];
            s2 += g_dpp[(size_t)(b * 32 + kc + 2) * 512 + d];
            s3 += g_dpp[(size_t)(b * 32 + kc + 3) * 512 + d];
        }
        add_s[tid] = (s0 + s1) + (s2 + s3) + b1[d];
        w2_s[tid]  = w2[d];
    }
}

// ---------------------------------------------------------------------------
// Kernel C: converter GEMM (cu=0). Grid 512, occ 2. (R11 version)
// smem: aux 4KB | A32 32KB | A16 16KB | B 2x16KB = 84KB.
// ---------------------------------------------------------------------------
static constexpr uint32_t AUX_SZ    = 4096;
static constexpr uint32_t C_OFF_A32 = AUX_SZ;
static constexpr uint32_t C_OFF_A16 = C_OFF_A32 + 32768;
static constexpr uint32_t C_OFF_B   = C_OFF_A16 + 16384;
static constexpr uint32_t SMEM_CONV = C_OFF_B + 32768;   // 86016

__global__ void __launch_bounds__(256, 2)
attn_conv_kernel(const float* __restrict__ enc, const float* __restrict__ b1,
                 const float* __restrict__ w2) {
    extern __shared__ char sm[];
    float* add_s = (float*)sm;
    float* w2_s  = (float*)(sm + 512);
    float* spart = (float*)(sm + 1024);
    const uint32_t smu  = smem_u32(sm);
    const uint32_t a32u = smu + C_OFF_A32;
    const uint32_t a16u = smu + C_OFF_A16;
    const uint32_t bu   = smu + C_OFF_B;

    const int tid  = threadIdx.x;
    const int lane = tid & 31, wid = tid >> 5;
    const int wm   = wid & 1, wn = wid >> 1;
    const int quad = lane >> 2, qlane = lane & 3;
    const int lane7 = lane & 7;

    const int rc = blockIdx.x;                 // 0..511
    const size_t row0 = (size_t)rc * 128;
    const float* gA = enc + row0 * 512;
    const __nv_bfloat16* gB = g_W1Tb;          // cu = 0
    const int b = rc >> 4;

    load_addw2(add_s, w2_s, b, 0, b1, w2, tid);

    auto prefetchA = [&](int t) {
        const float* src = gA + t * 64;
#pragma unroll
        for (int p = 0; p < 8; p++) {
            int slot = tid + p * 256;
            int r = slot >> 4, c = slot & 15;
            cp_async16(a32u + (uint32_t)slot * 16, src + (size_t)r * 512 + c * 4);
        }
    };
    auto prefetchB = [&](int t) {
        uint32_t dst = bu + (uint32_t)(t & 1) * 16384;
        const __nv_bfloat16* src = gB + t * 64;
#pragma unroll
        for (int p = 0; p < 4; p++) {
            int slot = tid + p * 256;
            int r = slot >> 3, blk = slot & 7;
            cp_async16(dst + (uint32_t)(r * 128 + ((blk ^ (r & 7)) << 4)),
                       src + (size_t)r * 512 + blk * 8);
        }
    };

    prefetchA(0); prefetchB(0); CP_COMMIT();

    float acc[4][4][4];
#pragma unroll
    for (int mf = 0; mf < 4; mf++)
#pragma unroll
        for (int nf = 0; nf < 4; nf++)
#pragma unroll
            for (int k = 0; k < 4; k++) acc[mf][nf][k] = 0.f;

    const uint32_t a_row = (uint32_t)(wm * 64 + ((lane >> 3) & 1) * 8 + lane7);
    const uint32_t b_row = (uint32_t)(wn * 32 + (lane >> 4) * 8 + lane7);
    const int cv_r0 = tid >> 4, cv_c = tid & 15;
    char* genc_rc = g_encb + (size_t)rc * 131072;

#pragma unroll 1
    for (int i = 0; i < 8; i++) {
        CP_WAIT(0);
        __syncthreads();

        // convert A32 -> A16 (swizzled) and mirror to g_encb (R11 path)
        char* gdst = genc_rc + (size_t)i * 16384;
#pragma unroll
        for (int p = 0; p < 8; p++) {
            int r = cv_r0 + p * 16;
            float4 v = *(const float4*)(sm + C_OFF_A32 + (uint32_t)(r * 256 + cv_c * 16));
            __nv_bfloat162 q0 = __float22bfloat162_rn({v.x, v.y});
            __nv_bfloat162 q1 = __float22bfloat162_rn({v.z, v.w});
            uint2 o;
            o.x = *(uint32_t*)&q0; o.y = *(uint32_t*)&q1;
            uint32_t off = (uint32_t)(r * 128 + (((cv_c >> 1) ^ (r & 7)) << 4) + (cv_c & 1) * 8);
            *(uint2*)(sm + C_OFF_A16 + off) = o;
            *(uint2*)(gdst + off) = o;
        }
        __syncthreads();

        if (i < 7) { prefetchA(i + 1); prefetchB(i + 1); CP_COMMIT(); }
        else CP_COMMIT();

        uint32_t sB = bu + (uint32_t)(i & 1) * 16384;
#pragma unroll
        for (int kf = 0; kf < 4; kf++) {
            uint32_t afr[4][4], bfr[4][2];
            uint32_t ablk = (uint32_t)(((kf * 2 + (lane >> 4)) ^ lane7) << 4);
            uint32_t bblk = (uint32_t)(((kf * 2 + ((lane >> 3) & 1)) ^ lane7) << 4);
#pragma unroll
            for (int mf = 0; mf < 4; mf++)
                ldmatrix_x4(afr[mf], a16u + (a_row + mf * 16) * 128 + ablk);
#pragma unroll
            for (int j = 0; j < 2; j++) {
                uint32_t r[4];
                ldmatrix_x4(r, sB + (b_row + j * 16) * 128 + bblk);
                bfr[2 * j][0] = r[0];     bfr[2 * j][1] = r[1];
                bfr[2 * j + 1][0] = r[2]; bfr[2 * j + 1][1] = r[3];
            }
#pragma unroll
            for (int mf = 0; mf < 4; mf++)
#pragma unroll
                for (int nf = 0; nf < 4; nf++)
                    mma_bf16(acc[mf][nf], afr[mf], bfr[nf]);
        }
    }

    // epilogue (cu = 0)
#pragma unroll
    for (int mf = 0; mf < 4; mf++) {
        float s0 = 0.f, s1 = 0.f;
#pragma unroll
        for (int nf = 0; nf < 4; nf++) {
            int c = wn * 32 + nf * 8 + qlane * 2;
            float a0 = add_s[c], a1 = add_s[c + 1];
            float v0 = w2_s[c],  v1 = w2_s[c + 1];
            s0 = fmaf(tanh_fast(acc[mf][nf][0] + a0), v0, s0);
            s0 = fmaf(tanh_fast(acc[mf][nf][1] + a1), v1, s0);
            s1 = fmaf(tanh_fast(acc[mf][nf][2] + a0), v0, s1);
            s1 = fmaf(tanh_fast(acc[mf][nf][3] + a1), v1, s1);
        }
        s0 += __shfl_xor_sync(0xffffffffu, s0, 1);
        s0 += __shfl_xor_sync(0xffffffffu, s0, 2);
        s1 += __shfl_xor_sync(0xffffffffu, s1, 1);
        s1 += __shfl_xor_sync(0xffffffffu, s1, 2);
        if (qlane == 0) {
            int r = wm * 64 + mf * 16 + quad;
            spart[wn * 128 + r]     = s0;
            spart[wn * 128 + r + 8] = s1;
        }
    }
    __syncthreads();
    if (tid < 128)
        g_spart[row0 + tid] =
            spart[tid] + spart[128 + tid] + spart[256 + tid] + spart[384 + tid];
}

// ---------------------------------------------------------------------------
// Kernel F: fast GEMM (cu=1..3). Grid 1536, rc-major: rc=bid/3, cu=1+bid%3
// (3 consumers of an rc co-scheduled -> one L2 tile read serves 3 CTAs).
// smem: aux 4KB | A16 3x16KB | B 3x16KB = 100KB, occ 2.
// ---------------------------------------------------------------------------
static constexpr uint32_t F_OFF_A16 = AUX_SZ;
static constexpr uint32_t F_OFF_B   = F_OFF_A16 + 49152;
static constexpr uint32_t SMEM_FAST = F_OFF_B + 49152;   // 102400

__global__ void __launch_bounds__(256, 2)
attn_fast_kernel(const float* __restrict__ b1, const float* __restrict__ w2) {
    extern __shared__ char sm[];
    float* add_s = (float*)sm;
    float* w2_s  = (float*)(sm + 512);
    float* spart = (float*)(sm + 1024);
    const uint32_t smu  = smem_u32(sm);
    const uint32_t a16u = smu + F_OFF_A16;
    const uint32_t bu   = smu + F_OFF_B;

    const int tid  = threadIdx.x;
    const int lane = tid & 31, wid = tid >> 5;
    const int wm   = wid & 1, wn = wid >> 1;
    const int quad = lane >> 2, qlane = lane & 3;
    const int lane7 = lane & 7;

    const int rc = blockIdx.x / 3;             // rc-major grouping
    const int cu = 1 + blockIdx.x % 3;         // 1..3
    const size_t row0 = (size_t)rc * 128;
    const char* gA = g_encb + (size_t)rc * 131072;
    const __nv_bfloat16* gB = g_W1Tb + (size_t)(cu * 128) * 512;
    const int b = rc >> 4;

    load_addw2(add_s, w2_s, b, cu, b1, w2, tid);

    auto prefetch = [&](int t) {
        uint32_t sA = a16u + (uint32_t)(t % 3) * 16384;
        uint32_t sB = bu + (uint32_t)(t % 3) * 16384;
        const char* srcA = gA + (size_t)t * 16384;
        const __nv_bfloat16* srcB = gB + t * 64;
#pragma unroll
        for (int p = 0; p < 4; p++) {
            int slot = tid + p * 256;
            cp_async16(sA + (uint32_t)slot * 16, srcA + (size_t)slot * 16);
            int r = slot >> 3, blk = slot & 7;
            cp_async16(sB + (uint32_t)(r * 128 + ((blk ^ (r & 7)) << 4)),
                       srcB + (size_t)r * 512 + blk * 8);
        }
        CP_COMMIT();
    };

    prefetch(0); prefetch(1);

    float acc[4][4][4];
#pragma unroll
    for (int mf = 0; mf < 4; mf++)
#pragma unroll
        for (int nf = 0; nf < 4; nf++)
#pragma unroll
            for (int k = 0; k < 4; k++) acc[mf][nf][k] = 0.f;

    const uint32_t a_row = (uint32_t)(wm * 64 + ((lane >> 3) & 1) * 8 + lane7);
    const uint32_t b_row = (uint32_t)(wn * 32 + (lane >> 4) * 8 + lane7);

#pragma unroll 1
    for (int i = 0; i < 8; i++) {
        CP_WAIT(1);
        __syncthreads();
        uint32_t sA = a16u + (uint32_t)(i % 3) * 16384;
        uint32_t sB = bu + (uint32_t)(i % 3) * 16384;

#pragma unroll
        for (int kf = 0; kf < 4; kf++) {
            uint32_t afr[4][4], bfr[4][2];
            uint32_t ablk = (uint32_t)(((kf * 2 + (lane >> 4)) ^ lane7) << 4);
            uint32_t bblk = (uint32_t)(((kf * 2 + ((lane >> 3) & 1)) ^ lane7) << 4);
#pragma unroll
            for (int mf = 0; mf < 4; mf++)
                ldmatrix_x4(afr[mf], sA + (a_row + mf * 16) * 128 + ablk);
#pragma unroll
            for (int j = 0; j < 2; j++) {
                uint32_t r[4];
                ldmatrix_x4(r, sB + (b_row + j * 16) * 128 + bblk);
                bfr[2 * j][0] = r[0];     bfr[2 * j][1] = r[1];
                bfr[2 * j + 1][0] = r[2]; bfr[2 * j + 1][1] = r[3];
            }
#pragma unroll
            for (int mf = 0; mf < 4; mf++)
#pragma unroll
                for (int nf = 0; nf < 4; nf++)
                    mma_bf16(acc[mf][nf], afr[mf], bfr[nf]);
        }

        if (i + 2 < 8) prefetch(i + 2);
        else CP_COMMIT();
    }
    CP_WAIT(0);

    // epilogue
#pragma unroll
    for (int mf = 0; mf < 4; mf++) {
        float s0 = 0.f, s1 = 0.f;
#pragma unroll
        for (int nf = 0; nf < 4; nf++) {
            int c = wn * 32 + nf * 8 + qlane * 2;
            float a0 = add_s[c], a1 = add_s[c + 1];
            float v0 = w2_s[c],  v1 = w2_s[c + 1];
            s0 = fmaf(tanh_fast(acc[mf][nf][0] + a0), v0, s0);
            s0 = fmaf(tanh_fast(acc[mf][nf][1] + a1), v1, s0);
            s1 = fmaf(tanh_fast(acc[mf][nf][2] + a0), v0, s1);
            s1 = fmaf(tanh_fast(acc[mf][nf][3] + a1), v1, s1);
        }
        s0 += __shfl_xor_sync(0xffffffffu, s0, 1);
        s0 += __shfl_xor_sync(0xffffffffu, s0, 2);
        s1 += __shfl_xor_sync(0xffffffffu, s1, 1);
        s1 += __shfl_xor_sync(0xffffffffu, s1, 2);
        if (qlane == 0) {
            int r = wm * 64 + mf * 16 + quad;
            spart[wn * 128 + r]     = s0;
            spart[wn * 128 + r + 8] = s1;
        }
    }
    __syncthreads();
    if (tid < 128)
        g_spart[(size_t)cu * 65536 + row0 + tid] =
            spart[tid] + spart[128 + tid] + spart[256 + tid] + spart[384 + tid];
}

// ---------------------------------------------------------------------------
// Kernel S: sum 4 partials + row softmax. 32 blocks x 1024 threads.
// ---------------------------------------------------------------------------
__global__ void __launch_bounds__(1024) softmax_kernel(float* __restrict__ out) {
    __shared__ float red[32];
    int b = blockIdx.x, t = threadIdx.x;
    int lane = t & 31, w = t >> 5;
    size_t i0 = (size_t)b * 2048 + t;
    size_t i1 = i0 + 1024;
    float v0 = g_spart[i0] + g_spart[65536 + i0] + g_spart[131072 + i0] + g_spart[196608 + i0];
    float v1 = g_spart[i1] + g_spart[65536 + i1] + g_spart[131072 + i1] + g_spart[196608 + i1];

    float vmax = fmaxf(v0, v1);
#pragma unroll
    for (int off = 16; off > 0; off >>= 1)
        vmax = fmaxf(vmax, __shfl_xor_sync(0xffffffffu, vmax, off));
    if (lane == 0) red[w] = vmax;
    __syncthreads();
    if (t < 32) {
        float m = red[t];
#pragma unroll
        for (int off = 16; off > 0; off >>= 1)
            m = fmaxf(m, __shfl_xor_sync(0xffffffffu, m, off));
        red[t] = m;
    }
    __syncthreads();
    vmax = red[0];
    __syncthreads();

    float e0 = __expf(v0 - vmax), e1 = __expf(v1 - vmax);
    float s = e0 + e1;
#pragma unroll
    for (int off = 16; off > 0; off >>= 1)
        s += __shfl_xor_sync(0xffffffffu, s, off);
    if (lane == 0) red[w] = s;
    __syncthreads();
    if (t < 32) {
        float m = red[t];
#pragma unroll
        for (int off = 16; off > 0; off >>= 1)
            m += __shfl_xor_sync(0xffffffffu, m, off);
        red[t] = m;
    }
    __syncthreads();
    float inv = 1.0f / red[0];

    out[i0] = e0 * inv;
    out[i1] = e1 * inv;
}

// ---------------------------------------------------------------------------
// kernel_launch — inputs: d_hidden, encoder_outputs, W1, b1, w2
// ---------------------------------------------------------------------------
extern "C" void kernel_launch(void* const* d_in, const int* in_sizes, int n_in,
                              void* d_out, int out_size) {
    const float* dh  = (const float*)d_in[0];  // (32, 2, 512)
    const float* enc = (const float*)d_in[1];  // (32, 2048, 512)
    const float* W1  = (const float*)d_in[2];  // (1536, 512)
    const float* b1  = (const float*)d_in[3];  // (512,)
    const float* w2  = (const float*)d_in[4];  // (512,)
    float* out = (float*)d_out;                // (32, 2048)

    cudaFuncSetAttribute(attn_conv_kernel, cudaFuncAttributeMaxDynamicSharedMemorySize,
                         (int)SMEM_CONV);
    cudaFuncSetAttribute(attn_fast_kernel, cudaFuncAttributeMaxDynamicSharedMemorySize,
                         (int)SMEM_FAST);

    prep_kernel<<<1280, 256>>>(W1, dh);
    attn_conv_kernel<<<512, 256, SMEM_CONV>>>(enc, b1, w2);
    attn_fast_kernel<<<1536, 256, SMEM_FAST>>>(b1, w2);
    softmax_kernel<<<32, 1024>>>(out);
}

// round 15
// speedup vs baseline: 1.0497x; 1.0011x over previous
#include <cuda_runtime.h>
#include <cuda_bf16.h>
#include <cstdint>

// ============================================================================
// scores[b,l] = sum_d tanh( (enc[b,l,:] @ W1_e)[d] + dec_proj[b,d] + b1[d] ) * w2[d]
// out = softmax(scores, axis=-1).  B=32, LIN=2048, E=D=512, nd=1024.
//
// R15: R14 with the fast GEMM rebuilt for crossbar relief:
//   128 thr/CTA, 2x2 warp grid, warp tile 64x64 (acc 128 regs), occ 2.
//   LDSM duplication drops A x4->x2, B x2->x2: 96KB -> 64KB per k-tile.
// Conv / prep / softmax / rc-major order: unchanged (measured-best).
// ============================================================================

__device__ __align__(16) __nv_bfloat16 g_W1Tb[512 * 512];   // W1_e^T bf16 [d][k]
__device__ __align__(16) float g_dpp[1024 * 512];           // dec_proj partials [b*32+kc][d]
__device__ __align__(16) float g_spart[4u * 65536u];        // per-colunit partial scores
__device__ __align__(16) char  g_encb[512u * 131072u];      // 64MB pre-swizzled bf16 A tiles

// ---------------------------------------------------------------------------
// helpers
// ---------------------------------------------------------------------------
__device__ __forceinline__ uint32_t smem_u32(const void* p) {
    uint32_t a;
    asm("{ .reg .u64 t; cvta.to.shared.u64 t, %1; cvt.u32.u64 %0, t; }" : "=r"(a) : "l"(p));
    return a;
}
__device__ __forceinline__ void cp_async16(uint32_t sdst, const void* gsrc) {
    asm volatile("cp.async.cg.shared.global [%0], [%1], 16;" :: "r"(sdst), "l"(gsrc) : "memory");
}
#define CP_COMMIT() asm volatile("cp.async.commit_group;" ::: "memory")
#define CP_WAIT(n)  asm volatile("cp.async.wait_group %0;" :: "n"(n) : "memory")

__device__ __forceinline__ float tanh_fast(float x) {
    float t;
    asm("tanh.approx.f32 %0, %1;" : "=f"(t) : "f"(x));
    return t;
}
__device__ __forceinline__ void ldmatrix_x4(uint32_t r[4], uint32_t addr) {
    asm volatile("ldmatrix.sync.aligned.m8n8.x4.shared.b16 {%0,%1,%2,%3}, [%4];"
                 : "=r"(r[0]), "=r"(r[1]), "=r"(r[2]), "=r"(r[3]) : "r"(addr));
}
__device__ __forceinline__ void mma_bf16(float c[4], const uint32_t a[4], const uint32_t b[2]) {
    asm volatile(
        "mma.sync.aligned.m16n8k16.row.col.f32.bf16.bf16.f32 "
        "{%0,%1,%2,%3}, {%4,%5,%6,%7}, {%8,%9}, {%0,%1,%2,%3};"
        : "+f"(c[0]), "+f"(c[1]), "+f"(c[2]), "+f"(c[3])
        : "r"(a[0]), "r"(a[1]), "r"(a[2]), "r"(a[3]), "r"(b[0]), "r"(b[1]));
}

// ---------------------------------------------------------------------------
// Kernel P: prep.
//   [0,1024): dec_proj partials (b x 32 k-chunks of 32); [1024,1280): W1_e^T.
// ---------------------------------------------------------------------------
__global__ void __launch_bounds__(256) prep_kernel(
    const float* __restrict__ W1, const float* __restrict__ dh) {
    int bid = blockIdx.x, tid = threadIdx.x;
    if (bid >= 1024) {
        __shared__ float tile[32][33];
        int v = bid - 1024;
        int d0 = (v & 15) * 32, k0 = (v >> 4) * 32;
        int tx = tid & 31, ty = tid >> 5;
#pragma unroll
        for (int j = 0; j < 32; j += 8)
            tile[ty + j][tx] = W1[(size_t)(1024 + k0 + ty + j) * 512 + d0 + tx];
        __syncthreads();
#pragma unroll
        for (int j = 0; j < 32; j += 8)
            g_W1Tb[(size_t)(d0 + ty + j) * 512 + k0 + tx] = __float2bfloat16_rn(tile[tx][ty + j]);
    } else {
        __shared__ float sdf[32];
        int b = bid >> 5, kc = bid & 31;
        int k0 = kc * 32;
        if (tid < 32) sdf[tid] = dh[b * 1024 + k0 + tid];
        __syncthreads();
        const float* w0 = W1 + (size_t)k0 * 512 + tid;
        const float* w1 = w0 + 256;
        float a[4] = {0.f, 0.f, 0.f, 0.f};
#pragma unroll 4
        for (int k = 0; k < 32; k += 2) {
            a[0] = fmaf(sdf[k],     w0[(size_t)k * 512],       a[0]);
            a[1] = fmaf(sdf[k + 1], w0[(size_t)(k + 1) * 512], a[1]);
            a[2] = fmaf(sdf[k],     w1[(size_t)k * 512],       a[2]);
            a[3] = fmaf(sdf[k + 1], w1[(size_t)(k + 1) * 512], a[3]);
        }
        g_dpp[(size_t)bid * 512 + tid]       = a[0] + a[1];
        g_dpp[(size_t)bid * 512 + tid + 256] = a[2] + a[3];
    }
}

// shared add_s/w2_s loader (sums 32 partials); call with >=128 threads
__device__ __forceinline__ void load_addw2(float* add_s, float* w2_s, int b, int cu,
                                           const float* b1, const float* w2, int tid) {
    if (tid < 128) {
        int d = cu * 128 + tid;
        float s0 = 0.f, s1 = 0.f, s2 = 0.f, s3 = 0.f;
#pragma unroll
        for (int kc = 0; kc < 32; kc += 4) {
            s0 += g_dpp[(size_t)(b * 32 + kc + 0) * 512 + d];
            s1 += g_dpp[(size_t)(b * 32 + kc + 1) * 512 + d];
            s2 += g_dpp[(size_t)(b * 32 + kc + 2) * 512 + d];
            s3 += g_dpp[(size_t)(b * 32 + kc + 3) * 512 + d];
        }
        add_s[tid] = (s0 + s1) + (s2 + s3) + b1[d];
        w2_s[tid]  = w2[d];
    }
}

// ---------------------------------------------------------------------------
// Kernel C: converter GEMM (cu=0). Grid 512, 256 thr, occ 2. (R11/R14 version)
// smem: aux 4KB | A32 32KB | A16 16KB | B 2x16KB = 84KB.
// ---------------------------------------------------------------------------
static constexpr uint32_t AUX_SZ    = 4096;
static constexpr uint32_t C_OFF_A32 = AUX_SZ;
static constexpr uint32_t C_OFF_A16 = C_OFF_A32 + 32768;
static constexpr uint32_t C_OFF_B   = C_OFF_A16 + 16384;
static constexpr uint32_t SMEM_CONV = C_OFF_B + 32768;   // 86016

__global__ void __launch_bounds__(256, 2)
attn_conv_kernel(const float* __restrict__ enc, const float* __restrict__ b1,
                 const float* __restrict__ w2) {
    extern __shared__ char sm[];
    float* add_s = (float*)sm;
    float* w2_s  = (float*)(sm + 512);
    float* spart = (float*)(sm + 1024);
    const uint32_t smu  = smem_u32(sm);
    const uint32_t a32u = smu + C_OFF_A32;
    const uint32_t a16u = smu + C_OFF_A16;
    const uint32_t bu   = smu + C_OFF_B;

    const int tid  = threadIdx.x;
    const int lane = tid & 31, wid = tid >> 5;
    const int wm   = wid & 1, wn = wid >> 1;
    const int quad = lane >> 2, qlane = lane & 3;
    const int lane7 = lane & 7;

    const int rc = blockIdx.x;                 // 0..511
    const size_t row0 = (size_t)rc * 128;
    const float* gA = enc + row0 * 512;
    const __nv_bfloat16* gB = g_W1Tb;          // cu = 0
    const int b = rc >> 4;

    load_addw2(add_s, w2_s, b, 0, b1, w2, tid);

    auto prefetchA = [&](int t) {
        const float* src = gA + t * 64;
#pragma unroll
        for (int p = 0; p < 8; p++) {
            int slot = tid + p * 256;
            int r = slot >> 4, c = slot & 15;
            cp_async16(a32u + (uint32_t)slot * 16, src + (size_t)r * 512 + c * 4);
        }
    };
    auto prefetchB = [&](int t) {
        uint32_t dst = bu + (uint32_t)(t & 1) * 16384;
        const __nv_bfloat16* src = gB + t * 64;
#pragma unroll
        for (int p = 0; p < 4; p++) {
            int slot = tid + p * 256;
            int r = slot >> 3, blk = slot & 7;
            cp_async16(dst + (uint32_t)(r * 128 + ((blk ^ (r & 7)) << 4)),
                       src + (size_t)r * 512 + blk * 8);
        }
    };

    prefetchA(0); prefetchB(0); CP_COMMIT();

    float acc[4][4][4];
#pragma unroll
    for (int mf = 0; mf < 4; mf++)
#pragma unroll
        for (int nf = 0; nf < 4; nf++)
#pragma unroll
            for (int k = 0; k < 4; k++) acc[mf][nf][k] = 0.f;

    const uint32_t a_row = (uint32_t)(wm * 64 + ((lane >> 3) & 1) * 8 + lane7);
    const uint32_t b_row = (uint32_t)(wn * 32 + (lane >> 4) * 8 + lane7);
    const int cv_r0 = tid >> 4, cv_c = tid & 15;
    char* genc_rc = g_encb + (size_t)rc * 131072;

#pragma unroll 1
    for (int i = 0; i < 8; i++) {
        CP_WAIT(0);
        __syncthreads();

        // convert A32 -> A16 (swizzled) and mirror to g_encb
        char* gdst = genc_rc + (size_t)i * 16384;
#pragma unroll
        for (int p = 0; p < 8; p++) {
            int r = cv_r0 + p * 16;
            float4 v = *(const float4*)(sm + C_OFF_A32 + (uint32_t)(r * 256 + cv_c * 16));
            __nv_bfloat162 q0 = __float22bfloat162_rn({v.x, v.y});
            __nv_bfloat162 q1 = __float22bfloat162_rn({v.z, v.w});
            uint2 o;
            o.x = *(uint32_t*)&q0; o.y = *(uint32_t*)&q1;
            uint32_t off = (uint32_t)(r * 128 + (((cv_c >> 1) ^ (r & 7)) << 4) + (cv_c & 1) * 8);
            *(uint2*)(sm + C_OFF_A16 + off) = o;
            *(uint2*)(gdst + off) = o;
        }
        __syncthreads();

        if (i < 7) { prefetchA(i + 1); prefetchB(i + 1); CP_COMMIT(); }
        else CP_COMMIT();

        uint32_t sB = bu + (uint32_t)(i & 1) * 16384;
#pragma unroll
        for (int kf = 0; kf < 4; kf++) {
            uint32_t afr[4][4], bfr[4][2];
            uint32_t ablk = (uint32_t)(((kf * 2 + (lane >> 4)) ^ lane7) << 4);
            uint32_t bblk = (uint32_t)(((kf * 2 + ((lane >> 3) & 1)) ^ lane7) << 4);
#pragma unroll
            for (int mf = 0; mf < 4; mf++)
                ldmatrix_x4(afr[mf], a16u + (a_row + mf * 16) * 128 + ablk);
#pragma unroll
            for (int j = 0; j < 2; j++) {
                uint32_t r[4];
                ldmatrix_x4(r, sB + (b_row + j * 16) * 128 + bblk);
                bfr[2 * j][0] = r[0];     bfr[2 * j][1] = r[1];
                bfr[2 * j + 1][0] = r[2]; bfr[2 * j + 1][1] = r[3];
            }
#pragma unroll
            for (int mf = 0; mf < 4; mf++)
#pragma unroll
                for (int nf = 0; nf < 4; nf++)
                    mma_bf16(acc[mf][nf], afr[mf], bfr[nf]);
        }
    }

    // epilogue (cu = 0)
#pragma unroll
    for (int mf = 0; mf < 4; mf++) {
        float s0 = 0.f, s1 = 0.f;
#pragma unroll
        for (int nf = 0; nf < 4; nf++) {
            int c = wn * 32 + nf * 8 + qlane * 2;
            float a0 = add_s[c], a1 = add_s[c + 1];
            float v0 = w2_s[c],  v1 = w2_s[c + 1];
            s0 = fmaf(tanh_fast(acc[mf][nf][0] + a0), v0, s0);
            s0 = fmaf(tanh_fast(acc[mf][nf][1] + a1), v1, s0);
            s1 = fmaf(tanh_fast(acc[mf][nf][2] + a0), v0, s1);
            s1 = fmaf(tanh_fast(acc[mf][nf][3] + a1), v1, s1);
        }
        s0 += __shfl_xor_sync(0xffffffffu, s0, 1);
        s0 += __shfl_xor_sync(0xffffffffu, s0, 2);
        s1 += __shfl_xor_sync(0xffffffffu, s1, 1);
        s1 += __shfl_xor_sync(0xffffffffu, s1, 2);
        if (qlane == 0) {
            int r = wm * 64 + mf * 16 + quad;
            spart[wn * 128 + r]     = s0;
            spart[wn * 128 + r + 8] = s1;
        }
    }
    __syncthreads();
    if (tid < 128)
        g_spart[row0 + tid] =
            spart[tid] + spart[128 + tid] + spart[256 + tid] + spart[384 + tid];
}

// ---------------------------------------------------------------------------
// Kernel F: fast GEMM (cu=1..3). Grid 1536, rc-major. 128 thr, 2x2 warp grid,
// warp tile 64x64, occ 2. LDSM per k-tile: 64KB (was 96KB).
// smem: aux 4KB | A16 3x16KB | B 3x16KB = 100KB.
// ---------------------------------------------------------------------------
static constexpr uint32_t F_OFF_A16 = AUX_SZ;
static constexpr uint32_t F_OFF_B   = F_OFF_A16 + 49152;
static constexpr uint32_t SMEM_FAST = F_OFF_B + 49152;   // 102400

__global__ void __launch_bounds__(128, 2)
attn_fast_kernel(const float* __restrict__ b1, const float* __restrict__ w2) {
    extern __shared__ char sm[];
    float* add_s = (float*)sm;                 // 128 f
    float* w2_s  = (float*)(sm + 512);         // 128 f
    float* spart = (float*)(sm + 1024);        // 2 x 128 f
    const uint32_t smu  = smem_u32(sm);
    const uint32_t a16u = smu + F_OFF_A16;
    const uint32_t bu   = smu + F_OFF_B;

    const int tid  = threadIdx.x;
    const int lane = tid & 31, wid = tid >> 5;
    const int wm   = wid & 1, wn = wid >> 1;   // 2m x 2n warp grid
    const int quad = lane >> 2, qlane = lane & 3;
    const int lane7 = lane & 7;

    const int rc = blockIdx.x / 3;             // rc-major grouping
    const int cu = 1 + blockIdx.x % 3;         // 1..3
    const size_t row0 = (size_t)rc * 128;
    const char* gA = g_encb + (size_t)rc * 131072;
    const __nv_bfloat16* gB = g_W1Tb + (size_t)(cu * 128) * 512;
    const int b = rc >> 4;

    load_addw2(add_s, w2_s, b, cu, b1, w2, tid);

    // 128 threads: 8 passes of 128 x 16B for each of A and B (16KB each)
    auto prefetch = [&](int t) {
        uint32_t sA = a16u + (uint32_t)(t % 3) * 16384;
        uint32_t sB = bu + (uint32_t)(t % 3) * 16384;
        const char* srcA = gA + (size_t)t * 16384;
        const __nv_bfloat16* srcB = gB + t * 64;
#pragma unroll
        for (int p = 0; p < 8; p++) {
            int slot = tid + p * 128;
            cp_async16(sA + (uint32_t)slot * 16, srcA + (size_t)slot * 16);
            int r = slot >> 3, blk = slot & 7;
            cp_async16(sB + (uint32_t)(r * 128 + ((blk ^ (r & 7)) << 4)),
                       srcB + (size_t)r * 512 + blk * 8);
        }
        CP_COMMIT();
    };

    prefetch(0); prefetch(1);

    float acc[4][8][4];
#pragma unroll
    for (int mf = 0; mf < 4; mf++)
#pragma unroll
        for (int nf = 0; nf < 8; nf++)
#pragma unroll
            for (int k = 0; k < 4; k++) acc[mf][nf][k] = 0.f;

    const uint32_t a_row = (uint32_t)(wm * 64 + ((lane >> 3) & 1) * 8 + lane7);
    const uint32_t b_row = (uint32_t)(wn * 64 + (lane >> 4) * 8 + lane7);

#pragma unroll 1
    for (int i = 0; i < 8; i++) {
        CP_WAIT(1);
        __syncthreads();
        uint32_t sA = a16u + (uint32_t)(i % 3) * 16384;
        uint32_t sB = bu + (uint32_t)(i % 3) * 16384;

#pragma unroll
        for (int kf = 0; kf < 4; kf++) {
            uint32_t afr[4][4], bfr[8][2];
            uint32_t ablk = (uint32_t)(((kf * 2 + (lane >> 4)) ^ lane7) << 4);
            uint32_t bblk = (uint32_t)(((kf * 2 + ((lane >> 3) & 1)) ^ lane7) << 4);
#pragma unroll
            for (int mf = 0; mf < 4; mf++)
                ldmatrix_x4(afr[mf], sA + (a_row + mf * 16) * 128 + ablk);
#pragma unroll
            for (int j = 0; j < 4; j++) {
                uint32_t r[4];
                ldmatrix_x4(r, sB + (b_row + j * 16) * 128 + bblk);
                bfr[2 * j][0] = r[0];     bfr[2 * j][1] = r[1];
                bfr[2 * j + 1][0] = r[2]; bfr[2 * j + 1][1] = r[3];
            }
#pragma unroll
            for (int mf = 0; mf < 4; mf++)
#pragma unroll
                for (int nf = 0; nf < 8; nf++)
                    mma_bf16(acc[mf][nf], afr[mf], bfr[nf]);
        }

        if (i + 2 < 8) prefetch(i + 2);
        else CP_COMMIT();
    }
    CP_WAIT(0);

    // epilogue: tanh(acc + add) * w2 over warp's 64 cols, reduce
#pragma unroll
    for (int mf = 0; mf < 4; mf++) {
        float s0 = 0.f, s1 = 0.f;
#pragma unroll
        for (int nf = 0; nf < 8; nf++) {
            int c = wn * 64 + nf * 8 + qlane * 2;
            float a0 = add_s[c], a1 = add_s[c + 1];
            float v0 = w2_s[c],  v1 = w2_s[c + 1];
            s0 = fmaf(tanh_fast(acc[mf][nf][0] + a0), v0, s0);
            s0 = fmaf(tanh_fast(acc[mf][nf][1] + a1), v1, s0);
            s1 = fmaf(tanh_fast(acc[mf][nf][2] + a0), v0, s1);
            s1 = fmaf(tanh_fast(acc[mf][nf][3] + a1), v1, s1);
        }
        s0 += __shfl_xor_sync(0xffffffffu, s0, 1);
        s0 += __shfl_xor_sync(0xffffffffu, s0, 2);
        s1 += __shfl_xor_sync(0xffffffffu, s1, 1);
        s1 += __shfl_xor_sync(0xffffffffu, s1, 2);
        if (qlane == 0) {
            int r = wm * 64 + mf * 16 + quad;
            spart[wn * 128 + r]     = s0;
            spart[wn * 128 + r + 8] = s1;
        }
    }
    __syncthreads();
    if (tid < 128)
        g_spart[(size_t)cu * 65536 + row0 + tid] = spart[tid] + spart[128 + tid];
}

// ---------------------------------------------------------------------------
// Kernel S: sum 4 partials + row softmax. 32 blocks x 1024 threads.
// ---------------------------------------------------------------------------
__global__ void __launch_bounds__(1024) softmax_kernel(float* __restrict__ out) {
    __shared__ float red[32];
    int b = blockIdx.x, t = threadIdx.x;
    int lane = t & 31, w = t >> 5;
    size_t i0 = (size_t)b * 2048 + t;
    size_t i1 = i0 + 1024;
    float v0 = g_spart[i0] + g_spart[65536 + i0] + g_spart[131072 + i0] + g_spart[196608 + i0];
    float v1 = g_spart[i1] + g_spart[65536 + i1] + g_spart[131072 + i1] + g_spart[196608 + i1];

    float vmax = fmaxf(v0, v1);
#pragma unroll
    for (int off = 16; off > 0; off >>= 1)
        vmax = fmaxf(vmax, __shfl_xor_sync(0xffffffffu, vmax, off));
    if (lane == 0) red[w] = vmax;
    __syncthreads();
    if (t < 32) {
        float m = red[t];
#pragma unroll
        for (int off = 16; off > 0; off >>= 1)
            m = fmaxf(m, __shfl_xor_sync(0xffffffffu, m, off));
        red[t] = m;
    }
    __syncthreads();
    vmax = red[0];
    __syncthreads();

    float e0 = __expf(v0 - vmax), e1 = __expf(v1 - vmax);
    float s = e0 + e1;
#pragma unroll
    for (int off = 16; off > 0; off >>= 1)
        s += __shfl_xor_sync(0xffffffffu, s, off);
    if (lane == 0) red[w] = s;
    __syncthreads();
    if (t < 32) {
        float m = red[t];
#pragma unroll
        for (int off = 16; off > 0; off >>= 1)
            m += __shfl_xor_sync(0xffffffffu, m, off);
        red[t] = m;
    }
    __syncthreads();
    float inv = 1.0f / red[0];

    out[i0] = e0 * inv;
    out[i1] = e1 * inv;
}

// ---------------------------------------------------------------------------
// kernel_launch — inputs: d_hidden, encoder_outputs, W1, b1, w2
// ---------------------------------------------------------------------------
extern "C" void kernel_launch(void* const* d_in, const int* in_sizes, int n_in,
                              void* d_out, int out_size) {
    const float* dh  = (const float*)d_in[0];  // (32, 2, 512)
    const float* enc = (const float*)d_in[1];  // (32, 2048, 512)
    const float* W1  = (const float*)d_in[2];  // (1536, 512)
    const float* b1  = (const float*)d_in[3];  // (512,)
    const float* w2  = (const float*)d_in[4];  // (512,)
    float* out = (float*)d_out;                // (32, 2048)

    cudaFuncSetAttribute(attn_conv_kernel, cudaFuncAttributeMaxDynamicSharedMemorySize,
                         (int)SMEM_CONV);
    cudaFuncSetAttribute(attn_fast_kernel, cudaFuncAttributeMaxDynamicSharedMemorySize,
                         (int)SMEM_FAST);

    prep_kernel<<<1280, 256>>>(W1, dh);
    attn_conv_kernel<<<512, 256, SMEM_CONV>>>(enc, b1, w2);
    attn_fast_kernel<<<1536, 128, SMEM_FAST>>>(b1, w2);
    softmax_kernel<<<32, 1024>>>(out);
}